// round 2
// baseline (speedup 1.0000x reference)
#include <cuda_runtime.h>
#include <math.h>

// Problem constants (fixed by setup_inputs: b=2, h=w=256, DIM=256, HEADS=8, 8x8 windows)
#define DIMC 256
#define NHEADS 8
#define HD 32
#define WSZ 64           // tokens per window
#define MAXB 2

// Scratch (allocation-free rule: __device__ globals)
__device__ float g_qkv[(size_t)MAXB * 65536 * 768]; // QKV projection output
__device__ float g_y[(size_t)MAXB * 65536 * 256];   // attention output (token-major)

// ---------------------------------------------------------------------------
// Tiled SGEMM with fused bias:  C[M,N] = A[M,K] * W[N,K]^T + bias[N]
// (torch Linear convention). M % BM == 0, N % BN == 0, K % BK == 0 assumed.
// ---------------------------------------------------------------------------
template <int BM, int BN, int BK, int TM, int TN>
__global__ __launch_bounds__((BM / TM) * (BN / TN))
void gemm_bias_kernel(const float* __restrict__ A,
                      const float* __restrict__ W,
                      const float* __restrict__ bias,
                      float* __restrict__ C,
                      int M, int N, int K) {
    __shared__ float As[BK][BM + 4];
    __shared__ float Bs[BK][BN + 4];

    const int nThreads = (BM / TM) * (BN / TN); // 256
    const int tid = threadIdx.x;
    const int m0 = blockIdx.y * BM;
    const int n0 = blockIdx.x * BN;

    const int tx = tid % (BN / TN); // 0..15
    const int ty = tid / (BN / TN); // 0..15

    float acc[TM][TN];
#pragma unroll
    for (int i = 0; i < TM; i++)
#pragma unroll
        for (int j = 0; j < TN; j++) acc[i][j] = 0.f;

    const int loadsA = (BM * BK) / (4 * nThreads); // 2
    const int loadsB = (BN * BK) / (4 * nThreads); // 2

    for (int k0 = 0; k0 < K; k0 += BK) {
        // A tile -> As (transposed: As[k][m])
#pragma unroll
        for (int l = 0; l < loadsA; l++) {
            int idx = tid + l * nThreads;      // float4 index
            int row = idx / (BK / 4);
            int c4 = idx % (BK / 4);
            float4 a = *reinterpret_cast<const float4*>(
                &A[(size_t)(m0 + row) * K + k0 + c4 * 4]);
            As[c4 * 4 + 0][row] = a.x;
            As[c4 * 4 + 1][row] = a.y;
            As[c4 * 4 + 2][row] = a.z;
            As[c4 * 4 + 3][row] = a.w;
        }
        // W tile -> Bs (transposed: Bs[k][n]); W is [N,K] row-major
#pragma unroll
        for (int l = 0; l < loadsB; l++) {
            int idx = tid + l * nThreads;
            int row = idx / (BK / 4);
            int c4 = idx % (BK / 4);
            float4 w = *reinterpret_cast<const float4*>(
                &W[(size_t)(n0 + row) * K + k0 + c4 * 4]);
            Bs[c4 * 4 + 0][row] = w.x;
            Bs[c4 * 4 + 1][row] = w.y;
            Bs[c4 * 4 + 2][row] = w.z;
            Bs[c4 * 4 + 3][row] = w.w;
        }
        __syncthreads();

#pragma unroll
        for (int kk = 0; kk < BK; kk++) {
            float ra[TM], rb[TN];
#pragma unroll
            for (int i = 0; i < TM; i += 4) {
                float4 v = *reinterpret_cast<const float4*>(&As[kk][ty * TM + i]);
                ra[i] = v.x; ra[i + 1] = v.y; ra[i + 2] = v.z; ra[i + 3] = v.w;
            }
#pragma unroll
            for (int j = 0; j < TN; j += 4) {
                float4 v = *reinterpret_cast<const float4*>(&Bs[kk][tx * TN + j]);
                rb[j] = v.x; rb[j + 1] = v.y; rb[j + 2] = v.z; rb[j + 3] = v.w;
            }
#pragma unroll
            for (int i = 0; i < TM; i++)
#pragma unroll
                for (int j = 0; j < TN; j++) acc[i][j] += ra[i] * rb[j];
        }
        __syncthreads();
    }

    // Write back with fused bias (vectorized)
#pragma unroll
    for (int i = 0; i < TM; i++) {
        int m = m0 + ty * TM + i;
#pragma unroll
        for (int j = 0; j < TN; j += 4) {
            int n = n0 + tx * TN + j;
            float4 r;
            r.x = acc[i][j + 0] + bias[n + 0];
            r.y = acc[i][j + 1] + bias[n + 1];
            r.z = acc[i][j + 2] + bias[n + 2];
            r.w = acc[i][j + 3] + bias[n + 3];
            *reinterpret_cast<float4*>(&C[(size_t)m * N + n]) = r;
        }
    }
}

// ---------------------------------------------------------------------------
// Fused window attention. One block per (window, head); 64 threads = 64 query
// rows. qkv layout: [token][768] with q=[0,256), k=[256,512), v=[512,768),
// channel = head*32 + d. Writes y[token][256].
// ---------------------------------------------------------------------------
__global__ __launch_bounds__(64)
void win_attn_kernel(const float* __restrict__ qkv,
                     const float* __restrict__ bias_table,
                     float* __restrict__ y) {
    __shared__ float ks[64][33];
    __shared__ float vs[64][33];
    __shared__ float bt[15 * 15 * NHEADS]; // 1800 floats

    const int gid = blockIdx.x;
    const int head = gid & 7;
    const int win = gid >> 3;
    const int wx = win & 31;
    const int wy = (win >> 5) & 31;
    const int bb = win >> 10;
    const int r = threadIdx.x; // query row within window (0..63)

    for (int i = r; i < 15 * 15 * NHEADS; i += 64) bt[i] = bias_table[i];

    const int iy = wy * 8 + (r >> 3);
    const int ix = wx * 8 + (r & 7);
    const size_t tok = ((size_t)bb << 16) + (size_t)iy * 256 + ix;
    const float* qp = qkv + tok * 768 + head * HD;

    float q[HD];
#pragma unroll
    for (int d = 0; d < HD; d += 4) {
        float4 a = *reinterpret_cast<const float4*>(&qp[d]);
        q[d] = a.x; q[d + 1] = a.y; q[d + 2] = a.z; q[d + 3] = a.w;
        float4 b = *reinterpret_cast<const float4*>(&qp[256 + d]);
        ks[r][d] = b.x; ks[r][d + 1] = b.y; ks[r][d + 2] = b.z; ks[r][d + 3] = b.w;
        float4 c = *reinterpret_cast<const float4*>(&qp[512 + d]);
        vs[r][d] = c.x; vs[r][d + 1] = c.y; vs[r][d + 2] = c.z; vs[r][d + 3] = c.w;
    }
    __syncthreads();

    const float scale = 0.17677669529663687f; // 1/sqrt(32)
    const int qi = r >> 3, qj = r & 7;

    float s[WSZ];
#pragma unroll
    for (int j = 0; j < WSZ; j++) {
        float a = 0.f;
#pragma unroll
        for (int d = 0; d < HD; d++) a += q[d] * ks[j][d];
        const int rel = (qi - (j >> 3) + 7) * 15 + (qj - (j & 7) + 7);
        s[j] = a * scale + bt[rel * NHEADS + head];
    }

    float mx = -1e30f;
#pragma unroll
    for (int j = 0; j < WSZ; j++) mx = fmaxf(mx, s[j]);
    float sum = 0.f;
#pragma unroll
    for (int j = 0; j < WSZ; j++) {
        s[j] = __expf(s[j] - mx);
        sum += s[j];
    }
    const float rs = 1.f / sum;

    float o[HD];
#pragma unroll
    for (int d = 0; d < HD; d++) o[d] = 0.f;
#pragma unroll
    for (int j = 0; j < WSZ; j++) {
        const float a = s[j];
#pragma unroll
        for (int d = 0; d < HD; d++) o[d] += a * vs[j][d];
    }

    float* yp = y + tok * DIMC + head * HD;
#pragma unroll
    for (int d = 0; d < HD; d += 4) {
        float4 v;
        v.x = o[d] * rs; v.y = o[d + 1] * rs;
        v.z = o[d + 2] * rs; v.w = o[d + 3] * rs;
        *reinterpret_cast<float4*>(&yp[d]) = v;
    }
}

// ---------------------------------------------------------------------------
extern "C" void kernel_launch(void* const* d_in, const int* in_sizes, int n_in,
                              void* d_out, int out_size) {
    // metadata order: x, h, w, wqkv_w, wqkv_b, wp_w, wp_b, bias_table
    const float* x = (const float*)d_in[0];
    const float* wqkv_w = (const float*)d_in[3];
    const float* wqkv_b = (const float*)d_in[4];
    const float* wp_w = (const float*)d_in[5];
    const float* wp_b = (const float*)d_in[6];
    const float* bias_table = (const float*)d_in[7];
    float* out = (float*)d_out;

    const int M = in_sizes[0] / DIMC; // b * 65536
    const int b = M / 65536;

    float* qkv = nullptr;
    float* ybuf = nullptr;
    cudaGetSymbolAddress((void**)&qkv, g_qkv);
    cudaGetSymbolAddress((void**)&ybuf, g_y);

    // 1) QKV projection: [M,256] x [768,256]^T -> [M,768]
    {
        dim3 grid(768 / 128, M / 128);
        gemm_bias_kernel<128, 128, 16, 8, 8><<<grid, 256>>>(
            x, wqkv_w, wqkv_b, qkv, M, 768, DIMC);
    }
    // 2) Window attention: one block per (window, head)
    {
        int nblocks = b * 32 * 32 * NHEADS;
        win_attn_kernel<<<nblocks, 64>>>(qkv, bias_table, ybuf);
    }
    // 3) Output projection: [M,256] x [256,256]^T -> [M,256]
    {
        dim3 grid(DIMC / 128, M / 128);
        gemm_bias_kernel<128, 128, 16, 8, 8><<<grid, 256>>>(
            ybuf, wp_w, wp_b, out, M, DIMC, DIMC);
    }
}

// round 5
// speedup vs baseline: 2.0067x; 2.0067x over previous
#include <cuda_runtime.h>
#include <math.h>

// Problem constants (fixed by setup_inputs: b=2, h=w=256, DIM=256, HEADS=8, 8x8 windows)
#define DIMC 256
#define NHEADS 8
#define HD 32
#define WSZ 64
#define MAXB 2

// Scratch (allocation-free rule: __device__ globals)
__device__ float g_qkv[(size_t)MAXB * 65536 * 768];  // QKV projection output (fp32)
__device__ float g_y[(size_t)MAXB * 65536 * 256];    // attention output (tf32-rounded fp32)
__device__ float g_xt[(size_t)MAXB * 65536 * 256];   // x converted to tf32-rounded fp32
__device__ float g_wqkvt[768 * 256];                 // wqkv_w tf32-rounded
__device__ float g_wpt[256 * 256];                   // wp_w tf32-rounded

// ---------------------------------------------------------------------------
// helpers
// ---------------------------------------------------------------------------
__device__ __forceinline__ float to_tf32(float x) {
    unsigned u;
    asm("cvt.rna.tf32.f32 %0, %1;" : "=r"(u) : "f"(x));
    return __uint_as_float(u);
}

__device__ __forceinline__ void cp16(unsigned saddr, const void* g) {
    asm volatile("cp.async.cg.shared.global [%0], [%1], 16;" :: "r"(saddr), "l"(g));
}

// ---------------------------------------------------------------------------
// elementwise tf32 rounding (float4 granular)
// ---------------------------------------------------------------------------
__global__ void tf32_convert_kernel(const float* __restrict__ in,
                                    float* __restrict__ out, int n4) {
    int i = blockIdx.x * blockDim.x + threadIdx.x;
    if (i < n4) {
        float4 v = reinterpret_cast<const float4*>(in)[i];
        v.x = to_tf32(v.x); v.y = to_tf32(v.y);
        v.z = to_tf32(v.z); v.w = to_tf32(v.w);
        reinterpret_cast<float4*>(out)[i] = v;
    }
}

// ---------------------------------------------------------------------------
// TF32 tensor-core GEMM with fused bias: C[M,N] = A[M,K] * W[N,K]^T + bias[N]
// A and W must already be tf32-rounded fp32. 128x128x32 block tile, 8 warps
// (2x4), warp tile 64x32 via 4x4 grid of m16n8k8 mma. cp.async double buffer.
// ---------------------------------------------------------------------------
#define GBM 128
#define GBN 128
#define GBK 32
#define GPAD 36  // smem row stride in floats (frag loads provably conflict-free)

__global__ __launch_bounds__(256, 2)
void gemm_tf32_kernel(const float* __restrict__ A, const float* __restrict__ W,
                      const float* __restrict__ bias, float* __restrict__ C,
                      int M, int N, int K) {
    extern __shared__ float smem[];
    float* As = smem;                    // [2][GBM][GPAD]
    float* Bs = smem + 2 * GBM * GPAD;   // [2][GBN][GPAD]

    const int tid = threadIdx.x;
    const int lane = tid & 31;
    const int warp = tid >> 5;
    const int wm = warp >> 2;  // 0..1
    const int wn = warp & 3;   // 0..3
    const long m0 = (long)blockIdx.y * GBM;
    const long n0 = (long)blockIdx.x * GBN;

    float acc[4][4][4];
#pragma unroll
    for (int mt = 0; mt < 4; mt++)
#pragma unroll
        for (int nt = 0; nt < 4; nt++)
#pragma unroll
            for (int r = 0; r < 4; r++) acc[mt][nt][r] = 0.f;

    const unsigned sA = (unsigned)__cvta_generic_to_shared(As);
    const unsigned sB = (unsigned)__cvta_generic_to_shared(Bs);

    const int NIT = K / GBK;

    // issue tile `it` into stage
    auto issue = [&](int it, int stage) {
        const int k0 = it * GBK;
#pragma unroll
        for (int l = 0; l < 4; l++) {
            int idx = tid + l * 256;
            int r = idx >> 3;       // 0..127
            int c4 = idx & 7;       // 0..7 (float4 within 32-wide row)
            cp16(sA + (((stage * GBM + r) * GPAD + c4 * 4) << 2),
                 A + (m0 + r) * K + k0 + c4 * 4);
            cp16(sB + (((stage * GBN + r) * GPAD + c4 * 4) << 2),
                 W + (n0 + r) * K + k0 + c4 * 4);
        }
        asm volatile("cp.async.commit_group;");
    };

    issue(0, 0);

    for (int it = 0; it < NIT; ++it) {
        if (it + 1 < NIT) {
            issue(it + 1, (it + 1) & 1);
            asm volatile("cp.async.wait_group 1;");
        } else {
            asm volatile("cp.async.wait_group 0;");
        }
        __syncthreads();

        const float* AsS = As + (it & 1) * GBM * GPAD;
        const float* BsS = Bs + (it & 1) * GBN * GPAD;

#pragma unroll
        for (int kk = 0; kk < GBK; kk += 8) {
            unsigned af[4][4], bf[4][2];
#pragma unroll
            for (int mt = 0; mt < 4; mt++) {
                int r = wm * 64 + mt * 16 + (lane >> 2);
                int c = kk + (lane & 3);
                af[mt][0] = __float_as_uint(AsS[r * GPAD + c]);
                af[mt][1] = __float_as_uint(AsS[(r + 8) * GPAD + c]);
                af[mt][2] = __float_as_uint(AsS[r * GPAD + c + 4]);
                af[mt][3] = __float_as_uint(AsS[(r + 8) * GPAD + c + 4]);
            }
#pragma unroll
            for (int nt = 0; nt < 4; nt++) {
                int n = wn * 32 + nt * 8 + (lane >> 2);
                int c = kk + (lane & 3);
                bf[nt][0] = __float_as_uint(BsS[n * GPAD + c]);
                bf[nt][1] = __float_as_uint(BsS[n * GPAD + c + 4]);
            }
#pragma unroll
            for (int mt = 0; mt < 4; mt++)
#pragma unroll
                for (int nt = 0; nt < 4; nt++)
                    asm volatile(
                        "mma.sync.aligned.m16n8k8.row.col.f32.tf32.tf32.f32 "
                        "{%0,%1,%2,%3}, {%4,%5,%6,%7}, {%8,%9}, {%0,%1,%2,%3};"
                        : "+f"(acc[mt][nt][0]), "+f"(acc[mt][nt][1]),
                          "+f"(acc[mt][nt][2]), "+f"(acc[mt][nt][3])
                        : "r"(af[mt][0]), "r"(af[mt][1]),
                          "r"(af[mt][2]), "r"(af[mt][3]),
                          "r"(bf[nt][0]), "r"(bf[nt][1]));
        }
        __syncthreads();
    }

    // Epilogue with fused bias
#pragma unroll
    for (int mt = 0; mt < 4; mt++) {
        long r0 = m0 + wm * 64 + mt * 16 + (lane >> 2);
#pragma unroll
        for (int nt = 0; nt < 4; nt++) {
            long c = n0 + wn * 32 + nt * 8 + 2 * (lane & 3);
            float2 b2 = *reinterpret_cast<const float2*>(&bias[c]);
            float2 v0 = {acc[mt][nt][0] + b2.x, acc[mt][nt][1] + b2.y};
            float2 v1 = {acc[mt][nt][2] + b2.x, acc[mt][nt][3] + b2.y};
            *reinterpret_cast<float2*>(&C[r0 * N + c]) = v0;
            *reinterpret_cast<float2*>(&C[(r0 + 8) * N + c]) = v1;
        }
    }
}

// ---------------------------------------------------------------------------
// Fused window attention. One block per (window, head); 64 threads = 64 query
// rows. qkv layout: [token][768], q=[0,256) k=[256,512) v=[512,768),
// channel = head*32 + d. Writes y[token][256] tf32-rounded (feeds GEMM2).
// ---------------------------------------------------------------------------
__global__ __launch_bounds__(64)
void win_attn_kernel(const float* __restrict__ qkv,
                     const float* __restrict__ bias_table,
                     float* __restrict__ y) {
    __shared__ float ks[64][33];
    __shared__ float vs[64][33];
    __shared__ float bt[15 * 15 * NHEADS];

    const int gid = blockIdx.x;
    const int head = gid & 7;
    const int win = gid >> 3;
    const int wx = win & 31;
    const int wy = (win >> 5) & 31;
    const int bb = win >> 10;
    const int r = threadIdx.x;

    for (int i = r; i < 15 * 15 * NHEADS; i += 64) bt[i] = bias_table[i];

    const int iy = wy * 8 + (r >> 3);
    const int ix = wx * 8 + (r & 7);
    const size_t tok = ((size_t)bb << 16) + (size_t)iy * 256 + ix;
    const float* qp = qkv + tok * 768 + head * HD;

    float q[HD];
#pragma unroll
    for (int d = 0; d < HD; d += 4) {
        float4 a = *reinterpret_cast<const float4*>(&qp[d]);
        q[d] = a.x; q[d + 1] = a.y; q[d + 2] = a.z; q[d + 3] = a.w;
        float4 b = *reinterpret_cast<const float4*>(&qp[256 + d]);
        ks[r][d] = b.x; ks[r][d + 1] = b.y; ks[r][d + 2] = b.z; ks[r][d + 3] = b.w;
        float4 c = *reinterpret_cast<const float4*>(&qp[512 + d]);
        vs[r][d] = c.x; vs[r][d + 1] = c.y; vs[r][d + 2] = c.z; vs[r][d + 3] = c.w;
    }
    __syncthreads();

    const float scale = 0.17677669529663687f; // 1/sqrt(32)
    const int qi = r >> 3, qj = r & 7;

    float s[WSZ];
#pragma unroll
    for (int j = 0; j < WSZ; j++) {
        float a = 0.f;
#pragma unroll
        for (int d = 0; d < HD; d++) a += q[d] * ks[j][d];
        const int rel = (qi - (j >> 3) + 7) * 15 + (qj - (j & 7) + 7);
        s[j] = a * scale + bt[rel * NHEADS + head];
    }

    float mx = -1e30f;
#pragma unroll
    for (int j = 0; j < WSZ; j++) mx = fmaxf(mx, s[j]);
    float sum = 0.f;
#pragma unroll
    for (int j = 0; j < WSZ; j++) {
        s[j] = __expf(s[j] - mx);
        sum += s[j];
    }
    const float rs = 1.f / sum;

    float o[HD];
#pragma unroll
    for (int d = 0; d < HD; d++) o[d] = 0.f;
#pragma unroll
    for (int j = 0; j < WSZ; j++) {
        const float a = s[j];
#pragma unroll
        for (int d = 0; d < HD; d++) o[d] += a * vs[j][d];
    }

    float* yp = y + tok * DIMC + head * HD;
#pragma unroll
    for (int d = 0; d < HD; d += 4) {
        float4 v;
        v.x = to_tf32(o[d] * rs);
        v.y = to_tf32(o[d + 1] * rs);
        v.z = to_tf32(o[d + 2] * rs);
        v.w = to_tf32(o[d + 3] * rs);
        *reinterpret_cast<float4*>(&yp[d]) = v;
    }
}

// ---------------------------------------------------------------------------
extern "C" void kernel_launch(void* const* d_in, const int* in_sizes, int n_in,
                              void* d_out, int out_size) {
    // metadata order: x, h, w, wqkv_w, wqkv_b, wp_w, wp_b, bias_table
    const float* x = (const float*)d_in[0];
    const float* wqkv_w = (const float*)d_in[3];
    const float* wqkv_b = (const float*)d_in[4];
    const float* wp_w = (const float*)d_in[5];
    const float* wp_b = (const float*)d_in[6];
    const float* bias_table = (const float*)d_in[7];
    float* out = (float*)d_out;

    const int M = in_sizes[0] / DIMC;  // b * 65536
    const int b = M / 65536;

    float *qkv, *ybuf, *xt, *wqkvt, *wpt;
    cudaGetSymbolAddress((void**)&qkv, g_qkv);
    cudaGetSymbolAddress((void**)&ybuf, g_y);
    cudaGetSymbolAddress((void**)&xt, g_xt);
    cudaGetSymbolAddress((void**)&wqkvt, g_wqkvt);
    cudaGetSymbolAddress((void**)&wpt, g_wpt);

    const int smemBytes = 2 * (GBM + GBN) * GPAD * 4;  // 73728
    cudaFuncSetAttribute(gemm_tf32_kernel,
                         cudaFuncAttributeMaxDynamicSharedMemorySize, smemBytes);

    // 0) tf32-round inputs (x + both weights)
    {
        int n4 = M * (DIMC / 4);
        tf32_convert_kernel<<<(n4 + 255) / 256, 256>>>(x, xt, n4);
        int w4 = 768 * (DIMC / 4);
        tf32_convert_kernel<<<(w4 + 255) / 256, 256>>>(wqkv_w, wqkvt, w4);
        int p4 = DIMC * (DIMC / 4);
        tf32_convert_kernel<<<(p4 + 255) / 256, 256>>>(wp_w, wpt, p4);
    }
    // 1) QKV projection: [M,256] x [768,256]^T -> [M,768]
    {
        dim3 grid(768 / GBN, M / GBM);
        gemm_tf32_kernel<<<grid, 256, smemBytes>>>(xt, wqkvt, wqkv_b, qkv,
                                                   M, 768, DIMC);
    }
    // 2) Window attention
    {
        int nblocks = b * 32 * 32 * NHEADS;
        win_attn_kernel<<<nblocks, 64>>>(qkv, bias_table, ybuf);
    }
    // 3) Output projection: [M,256] x [256,256]^T -> [M,256]
    {
        dim3 grid(DIMC / GBN, M / GBM);
        gemm_tf32_kernel<<<grid, 256, smemBytes>>>(ybuf, wpt, wp_b, out,
                                                   M, DIMC, DIMC);
    }
}

// round 8
// speedup vs baseline: 2.3779x; 1.1850x over previous
#include <cuda_runtime.h>
#include <cuda_fp16.h>
#include <math.h>
#include <stdint.h>

// Problem constants (fixed: b=2, h=w=256, DIM=256, HEADS=8, 8x8 windows)
#define DIMC 256
#define NHEADS 8
#define HD 32
#define WSZ 64
#define MAXB 2

// Scratch (allocation-free rule: __device__ globals)
__device__ float  g_qkv[(size_t)MAXB * 65536 * 768];   // QKV output (fp32, attention input)
__device__ __half g_y[(size_t)MAXB * 65536 * 256];     // attention output (fp16, GEMM2 A)
__device__ __half g_xh[(size_t)MAXB * 65536 * 256];    // x in fp16
__device__ __half g_wqkvh[768 * 256];                  // wqkv_w fp16
__device__ __half g_wph[256 * 256];                    // wp_w fp16

// ---------------------------------------------------------------------------
// helpers
// ---------------------------------------------------------------------------
__device__ __forceinline__ float to_tf32(float x) {
    unsigned u;
    asm("cvt.rna.tf32.f32 %0, %1;" : "=r"(u) : "f"(x));
    return __uint_as_float(u);
}
__device__ __forceinline__ void cp16(uint32_t saddr, const void* g) {
    asm volatile("cp.async.cg.shared.global [%0], [%1], 16;" :: "r"(saddr), "l"(g));
}

// fp32 -> fp16 convert (float4 -> 2x half2 per thread)
__global__ void f2h_convert_kernel(const float* __restrict__ in,
                                   __half* __restrict__ out, int n4) {
    int i = blockIdx.x * blockDim.x + threadIdx.x;
    if (i < n4) {
        float4 v = reinterpret_cast<const float4*>(in)[i];
        __half2 h0 = __floats2half2_rn(v.x, v.y);
        __half2 h1 = __floats2half2_rn(v.z, v.w);
        uint2 p;
        p.x = *reinterpret_cast<uint32_t*>(&h0);
        p.y = *reinterpret_cast<uint32_t*>(&h1);
        reinterpret_cast<uint2*>(out)[i] = p;
    }
}

// ---------------------------------------------------------------------------
// FP16 tensor-core GEMM, fp32 accum, fused bias:
//   C[M,N] = A[M,K](f16) * W[N,K](f16)^T + bias[N](f32)
// 128x128x32 block tile, 8 warps (2x4), warp tile 64x32 via 4x4 m16n8k16.
// cp.async double buffer. Fragment LDS: one 32-bit load = one fragment reg.
// ---------------------------------------------------------------------------
#define GBM 128
#define GBN 128
#define GBK 32
#define PADH 40  // smem row stride in halves (bank-conflict-free, proven)

__global__ __launch_bounds__(256, 2)
void gemm_f16_kernel(const __half* __restrict__ A, const __half* __restrict__ W,
                     const float* __restrict__ bias, float* __restrict__ C,
                     int M, int N, int K) {
    __shared__ __half As[2][GBM][PADH];
    __shared__ __half Bs[2][GBN][PADH];

    const int tid = threadIdx.x;
    const int lane = tid & 31;
    const int warp = tid >> 5;
    const int wm = warp >> 2;  // 0..1
    const int wn = warp & 3;   // 0..3
    const long m0 = (long)blockIdx.y * GBM;
    const long n0 = (long)blockIdx.x * GBN;

    float acc[4][4][4];
#pragma unroll
    for (int mt = 0; mt < 4; mt++)
#pragma unroll
        for (int nt = 0; nt < 4; nt++)
#pragma unroll
            for (int r = 0; r < 4; r++) acc[mt][nt][r] = 0.f;

    const int NIT = K / GBK;

    auto issue = [&](int it, int stage) {
        const int k0 = it * GBK;
#pragma unroll
        for (int l = 0; l < 2; l++) {
            int idx = tid + l * 256;   // 0..511
            int r = idx >> 2;          // 0..127
            int c = idx & 3;           // 16B chunk (8 halves)
            cp16((uint32_t)__cvta_generic_to_shared(&As[stage][r][c * 8]),
                 A + (m0 + r) * K + k0 + c * 8);
            cp16((uint32_t)__cvta_generic_to_shared(&Bs[stage][r][c * 8]),
                 W + (n0 + r) * K + k0 + c * 8);
        }
        asm volatile("cp.async.commit_group;" ::: "memory");
    };

    issue(0, 0);

    for (int it = 0; it < NIT; ++it) {
        if (it + 1 < NIT) {
            issue(it + 1, (it + 1) & 1);
            asm volatile("cp.async.wait_group 1;" ::: "memory");
        } else {
            asm volatile("cp.async.wait_group 0;" ::: "memory");
        }
        __syncthreads();

        const int st = it & 1;
        const int g4 = lane >> 2;      // 0..7
        const int t4 = (lane & 3) * 2; // 0,2,4,6

#pragma unroll
        for (int ks = 0; ks < GBK; ks += 16) {
            uint32_t af[4][4], bf[4][2];
#pragma unroll
            for (int mt = 0; mt < 4; mt++) {
                int r = wm * 64 + mt * 16 + g4;
                af[mt][0] = *reinterpret_cast<const uint32_t*>(&As[st][r][ks + t4]);
                af[mt][1] = *reinterpret_cast<const uint32_t*>(&As[st][r + 8][ks + t4]);
                af[mt][2] = *reinterpret_cast<const uint32_t*>(&As[st][r][ks + 8 + t4]);
                af[mt][3] = *reinterpret_cast<const uint32_t*>(&As[st][r + 8][ks + 8 + t4]);
            }
#pragma unroll
            for (int nt = 0; nt < 4; nt++) {
                int n = wn * 32 + nt * 8 + g4;
                bf[nt][0] = *reinterpret_cast<const uint32_t*>(&Bs[st][n][ks + t4]);
                bf[nt][1] = *reinterpret_cast<const uint32_t*>(&Bs[st][n][ks + 8 + t4]);
            }
#pragma unroll
            for (int mt = 0; mt < 4; mt++)
#pragma unroll
                for (int nt = 0; nt < 4; nt++)
                    asm volatile(
                        "mma.sync.aligned.m16n8k16.row.col.f32.f16.f16.f32 "
                        "{%0,%1,%2,%3}, {%4,%5,%6,%7}, {%8,%9}, {%0,%1,%2,%3};"
                        : "+f"(acc[mt][nt][0]), "+f"(acc[mt][nt][1]),
                          "+f"(acc[mt][nt][2]), "+f"(acc[mt][nt][3])
                        : "r"(af[mt][0]), "r"(af[mt][1]),
                          "r"(af[mt][2]), "r"(af[mt][3]),
                          "r"(bf[nt][0]), "r"(bf[nt][1]));
        }
        __syncthreads();
    }

    // Epilogue with fused bias
#pragma unroll
    for (int mt = 0; mt < 4; mt++) {
        long r0 = m0 + wm * 64 + mt * 16 + (lane >> 2);
#pragma unroll
        for (int nt = 0; nt < 4; nt++) {
            long c = n0 + wn * 32 + nt * 8 + 2 * (lane & 3);
            float2 b2 = *reinterpret_cast<const float2*>(&bias[c]);
            float2 v0 = {acc[mt][nt][0] + b2.x, acc[mt][nt][1] + b2.y};
            float2 v1 = {acc[mt][nt][2] + b2.x, acc[mt][nt][3] + b2.y};
            *reinterpret_cast<float2*>(&C[r0 * N + c]) = v0;
            *reinterpret_cast<float2*>(&C[(r0 + 8) * N + c]) = v1;
        }
    }
}

// ---------------------------------------------------------------------------
// Fused window attention (fp32 math, vectorized smem). One block per
// (window, head); 64 threads = 64 query rows. Writes y in fp16 (GEMM2 input).
// ---------------------------------------------------------------------------
__global__ __launch_bounds__(64)
void win_attn_kernel(const float* __restrict__ qkv,
                     const float* __restrict__ bias_table,
                     __half* __restrict__ y) {
    __shared__ float4 ks4[8][64];
    __shared__ float4 vs4[8][64];
    __shared__ float bt[15 * 15 * NHEADS];

    const int gid = blockIdx.x;
    const int head = gid & 7;
    const int win = gid >> 3;
    const int wx = win & 31;
    const int wy = (win >> 5) & 31;
    const int bb = win >> 10;
    const int r = threadIdx.x;

    for (int i = r; i < 15 * 15 * NHEADS; i += 64) bt[i] = bias_table[i];

    const int iy = wy * 8 + (r >> 3);
    const int ix = wx * 8 + (r & 7);
    const size_t tok = ((size_t)bb << 16) + (size_t)iy * 256 + ix;
    const float4* qp4 = reinterpret_cast<const float4*>(qkv + tok * 768 + head * HD);

    float4 q4[8];
#pragma unroll
    for (int d4 = 0; d4 < 8; d4++) {
        q4[d4] = qp4[d4];
        ks4[d4][r] = qp4[64 + d4];   // +256 floats
        vs4[d4][r] = qp4[128 + d4];  // +512 floats
    }
    __syncthreads();

    const float scale = 0.17677669529663687f; // 1/sqrt(32)
    const int qi = r >> 3, qj = r & 7;

    float s[WSZ];
#pragma unroll
    for (int j = 0; j < WSZ; j++) {
        float a = 0.f;
#pragma unroll
        for (int d4 = 0; d4 < 8; d4++) {
            float4 kk = ks4[d4][j];
            a += q4[d4].x * kk.x + q4[d4].y * kk.y +
                 q4[d4].z * kk.z + q4[d4].w * kk.w;
        }
        const int rel = (qi - (j >> 3) + 7) * 15 + (qj - (j & 7) + 7);
        s[j] = a * scale + bt[rel * NHEADS + head];
    }

    float mx = -1e30f;
#pragma unroll
    for (int j = 0; j < WSZ; j++) mx = fmaxf(mx, s[j]);
    float sum = 0.f;
#pragma unroll
    for (int j = 0; j < WSZ; j++) {
        s[j] = __expf(s[j] - mx);
        sum += s[j];
    }
    const float rs = 1.f / sum;

    float4 o4[8];
#pragma unroll
    for (int d4 = 0; d4 < 8; d4++) o4[d4] = make_float4(0.f, 0.f, 0.f, 0.f);
#pragma unroll
    for (int j = 0; j < WSZ; j++) {
        const float a = s[j];
#pragma unroll
        for (int d4 = 0; d4 < 8; d4++) {
            float4 vv = vs4[d4][j];
            o4[d4].x += a * vv.x; o4[d4].y += a * vv.y;
            o4[d4].z += a * vv.z; o4[d4].w += a * vv.w;
        }
    }

    // fp16 output (8 bytes per float4-pair of halves)
    uint2* yp = reinterpret_cast<uint2*>(y + tok * DIMC + head * HD);
#pragma unroll
    for (int d4 = 0; d4 < 8; d4++) {
        __half2 h0 = __floats2half2_rn(o4[d4].x * rs, o4[d4].y * rs);
        __half2 h1 = __floats2half2_rn(o4[d4].z * rs, o4[d4].w * rs);
        uint2 p;
        p.x = *reinterpret_cast<uint32_t*>(&h0);
        p.y = *reinterpret_cast<uint32_t*>(&h1);
        yp[d4] = p;
    }
}

// ---------------------------------------------------------------------------
extern "C" void kernel_launch(void* const* d_in, const int* in_sizes, int n_in,
                              void* d_out, int out_size) {
    // metadata order: x, h, w, wqkv_w, wqkv_b, wp_w, wp_b, bias_table
    const float* x = (const float*)d_in[0];
    const float* wqkv_w = (const float*)d_in[3];
    const float* wqkv_b = (const float*)d_in[4];
    const float* wp_w = (const float*)d_in[5];
    const float* wp_b = (const float*)d_in[6];
    const float* bias_table = (const float*)d_in[7];
    float* out = (float*)d_out;

    const int M = in_sizes[0] / DIMC;  // b * 65536
    const int b = M / 65536;

    float* qkv;
    __half *ybuf, *xh, *wqkvh, *wph;
    cudaGetSymbolAddress((void**)&qkv, g_qkv);
    cudaGetSymbolAddress((void**)&ybuf, g_y);
    cudaGetSymbolAddress((void**)&xh, g_xh);
    cudaGetSymbolAddress((void**)&wqkvh, g_wqkvh);
    cudaGetSymbolAddress((void**)&wph, g_wph);

    // 0) fp16 conversion of x and both weight matrices
    {
        int n4 = M * (DIMC / 4);
        f2h_convert_kernel<<<(n4 + 255) / 256, 256>>>(x, xh, n4);
        int w4 = 768 * (DIMC / 4);
        f2h_convert_kernel<<<(w4 + 255) / 256, 256>>>(wqkv_w, wqkvh, w4);
        int p4 = DIMC * (DIMC / 4);
        f2h_convert_kernel<<<(p4 + 255) / 256, 256>>>(wp_w, wph, p4);
    }
    // 1) QKV projection: [M,256](f16) x [768,256](f16)^T -> [M,768](f32)
    {
        dim3 grid(768 / GBN, M / GBM);
        gemm_f16_kernel<<<grid, 256>>>(xh, wqkvh, wqkv_b, qkv, M, 768, DIMC);
    }
    // 2) Window attention (fp32 math, fp16 output)
    {
        int nblocks = b * 32 * 32 * NHEADS;
        win_attn_kernel<<<nblocks, 64>>>(qkv, bias_table, ybuf);
    }
    // 3) Output projection: [M,256](f16) x [256,256](f16)^T -> [M,256](f32)
    {
        dim3 grid(DIMC / GBN, M / GBM);
        gemm_f16_kernel<<<grid, 256>>>(ybuf, wph, wp_b, out, M, DIMC, DIMC);
    }
}

// round 9
// speedup vs baseline: 3.3088x; 1.3915x over previous
#include <cuda_runtime.h>
#include <cuda_fp16.h>
#include <math.h>
#include <stdint.h>

// Problem constants (fixed: b=2, h=w=256, DIM=256, HEADS=8, 8x8 windows)
#define DIMC 256
#define NHEADS 8
#define HD 32
#define WSZ 64
#define MAXB 2

// Scratch (allocation-free rule: __device__ globals)
__device__ __half g_qkvh[(size_t)MAXB * 65536 * 768]; // QKV output (fp16)
__device__ __half g_y[(size_t)MAXB * 65536 * 256];    // attention output (fp16)
__device__ __half g_xh[(size_t)MAXB * 65536 * 256];   // x in fp16
__device__ __half g_wqkvh[768 * 256];                 // wqkv_w fp16
__device__ __half g_wph[256 * 256];                   // wp_w fp16

// ---------------------------------------------------------------------------
// helpers
// ---------------------------------------------------------------------------
__device__ __forceinline__ void cp16(uint32_t saddr, const void* g) {
    asm volatile("cp.async.cg.shared.global [%0], [%1], 16;" :: "r"(saddr), "l"(g));
}
__device__ __forceinline__ void mma16816(float* d, const uint32_t* a,
                                         const uint32_t* b) {
    asm volatile(
        "mma.sync.aligned.m16n8k16.row.col.f32.f16.f16.f32 "
        "{%0,%1,%2,%3}, {%4,%5,%6,%7}, {%8,%9}, {%0,%1,%2,%3};"
        : "+f"(d[0]), "+f"(d[1]), "+f"(d[2]), "+f"(d[3])
        : "r"(a[0]), "r"(a[1]), "r"(a[2]), "r"(a[3]), "r"(b[0]), "r"(b[1]));
}
__device__ __forceinline__ uint32_t packh2(float x, float y) {
    __half2 h = __floats2half2_rn(x, y);
    return *reinterpret_cast<uint32_t*>(&h);
}

// fp32 -> fp16 convert
__global__ void f2h_convert_kernel(const float* __restrict__ in,
                                   __half* __restrict__ out, int n4) {
    int i = blockIdx.x * blockDim.x + threadIdx.x;
    if (i < n4) {
        float4 v = reinterpret_cast<const float4*>(in)[i];
        uint2 p;
        p.x = packh2(v.x, v.y);
        p.y = packh2(v.z, v.w);
        reinterpret_cast<uint2*>(out)[i] = p;
    }
}

// ---------------------------------------------------------------------------
// FP16 tensor-core GEMM, fp32 accum, fused bias, templated output type:
//   C[M,N] = A[M,K](f16) * W[N,K](f16)^T + bias[N](f32)
// 128x128x32 block tile, 8 warps (2x4), warp tile 64x32 via 4x4 m16n8k16.
// ---------------------------------------------------------------------------
#define GBM 128
#define GBN 128
#define GBK 32
#define PADH 40

template <typename OutT>
__global__ __launch_bounds__(256, 2)
void gemm_f16_kernel(const __half* __restrict__ A, const __half* __restrict__ W,
                     const float* __restrict__ bias, OutT* __restrict__ C,
                     int M, int N, int K) {
    __shared__ __half As[2][GBM][PADH];
    __shared__ __half Bs[2][GBN][PADH];

    const int tid = threadIdx.x;
    const int lane = tid & 31;
    const int warp = tid >> 5;
    const int wm = warp >> 2;
    const int wn = warp & 3;
    const long m0 = (long)blockIdx.y * GBM;
    const long n0 = (long)blockIdx.x * GBN;

    float acc[4][4][4];
#pragma unroll
    for (int mt = 0; mt < 4; mt++)
#pragma unroll
        for (int nt = 0; nt < 4; nt++)
#pragma unroll
            for (int r = 0; r < 4; r++) acc[mt][nt][r] = 0.f;

    const int NIT = K / GBK;

    auto issue = [&](int it, int stage) {
        const int k0 = it * GBK;
#pragma unroll
        for (int l = 0; l < 2; l++) {
            int idx = tid + l * 256;
            int r = idx >> 2;
            int c = idx & 3;
            cp16((uint32_t)__cvta_generic_to_shared(&As[stage][r][c * 8]),
                 A + (m0 + r) * K + k0 + c * 8);
            cp16((uint32_t)__cvta_generic_to_shared(&Bs[stage][r][c * 8]),
                 W + (n0 + r) * K + k0 + c * 8);
        }
        asm volatile("cp.async.commit_group;" ::: "memory");
    };

    issue(0, 0);

    for (int it = 0; it < NIT; ++it) {
        if (it + 1 < NIT) {
            issue(it + 1, (it + 1) & 1);
            asm volatile("cp.async.wait_group 1;" ::: "memory");
        } else {
            asm volatile("cp.async.wait_group 0;" ::: "memory");
        }
        __syncthreads();

        const int st = it & 1;
        const int g4 = lane >> 2;
        const int t4 = (lane & 3) * 2;

#pragma unroll
        for (int ks = 0; ks < GBK; ks += 16) {
            uint32_t af[4][4], bf[4][2];
#pragma unroll
            for (int mt = 0; mt < 4; mt++) {
                int r = wm * 64 + mt * 16 + g4;
                af[mt][0] = *reinterpret_cast<const uint32_t*>(&As[st][r][ks + t4]);
                af[mt][1] = *reinterpret_cast<const uint32_t*>(&As[st][r + 8][ks + t4]);
                af[mt][2] = *reinterpret_cast<const uint32_t*>(&As[st][r][ks + 8 + t4]);
                af[mt][3] = *reinterpret_cast<const uint32_t*>(&As[st][r + 8][ks + 8 + t4]);
            }
#pragma unroll
            for (int nt = 0; nt < 4; nt++) {
                int n = wn * 32 + nt * 8 + g4;
                bf[nt][0] = *reinterpret_cast<const uint32_t*>(&Bs[st][n][ks + t4]);
                bf[nt][1] = *reinterpret_cast<const uint32_t*>(&Bs[st][n][ks + 8 + t4]);
            }
#pragma unroll
            for (int mt = 0; mt < 4; mt++)
#pragma unroll
                for (int nt = 0; nt < 4; nt++)
                    mma16816(acc[mt][nt], af[mt], bf[nt]);
        }
        __syncthreads();
    }

    // Epilogue with fused bias; OutT = float or __half
#pragma unroll
    for (int mt = 0; mt < 4; mt++) {
        long r0 = m0 + wm * 64 + mt * 16 + (lane >> 2);
#pragma unroll
        for (int nt = 0; nt < 4; nt++) {
            long c = n0 + wn * 32 + nt * 8 + 2 * (lane & 3);
            float2 b2 = *reinterpret_cast<const float2*>(&bias[c]);
            float v00 = acc[mt][nt][0] + b2.x, v01 = acc[mt][nt][1] + b2.y;
            float v10 = acc[mt][nt][2] + b2.x, v11 = acc[mt][nt][3] + b2.y;
            if (sizeof(OutT) == 4) {
                float2* p0 = reinterpret_cast<float2*>((float*)C + r0 * N + c);
                float2* p1 = reinterpret_cast<float2*>((float*)C + (r0 + 8) * N + c);
                *p0 = make_float2(v00, v01);
                *p1 = make_float2(v10, v11);
            } else {
                *reinterpret_cast<uint32_t*>((__half*)C + r0 * N + c) = packh2(v00, v01);
                *reinterpret_cast<uint32_t*>((__half*)C + (r0 + 8) * N + c) = packh2(v10, v11);
            }
        }
    }
}

// ---------------------------------------------------------------------------
// Tensor-core window attention. One block per window; 512 threads = 16 warps;
// warp = (head, query-half of 32 rows). fp16 mma for QK^T and P*V, fp32
// softmax on fragments, unnormalized P, 1/sum in epilogue. y out fp16.
// smem: Ks[8][64][40] (40960B) + Vt[8][32][72] (36864B) + bt[225*8]f32 (7200B)
// ---------------------------------------------------------------------------
#define ATT_SMEM (40960 + 36864 + 7200)

__global__ __launch_bounds__(512, 1)
void win_attn_mma_kernel(const __half* __restrict__ qkv,
                         const float* __restrict__ bias_table,
                         __half* __restrict__ y) {
    extern __shared__ char smraw[];
    __half* Ks = reinterpret_cast<__half*>(smraw);            // [8][64][40]
    __half* Vt = reinterpret_cast<__half*>(smraw + 40960);    // [8][32][72]
    float* bt = reinterpret_cast<float*>(smraw + 40960 + 36864);

    const int blk = blockIdx.x;
    const int wx = blk & 31, wy = (blk >> 5) & 31, bb = blk >> 10;
    const int tid = threadIdx.x;
    const size_t tokbase = ((size_t)bb << 16) + (size_t)wy * 8 * 256 + wx * 8;

    // ---- stage K (natural) and V (transposed) for all 8 heads ----
#pragma unroll
    for (int l = 0; l < 4; l++) {
        int idx = tid + l * 512;       // 0..2047
        int t = idx >> 5;              // token in window
        int u = idx & 31;              // uint4 within 256-half row
        int h = u >> 2;
        int d0 = (u & 3) * 8;
        size_t tok = tokbase + (size_t)(t >> 3) * 256 + (t & 7);
        const uint4* src = reinterpret_cast<const uint4*>(qkv + tok * 768);
        uint4 kk = src[32 + u];  // K region (+256 halves)
        *reinterpret_cast<uint4*>(&Ks[(h * 64 + t) * 40 + d0]) = kk;
        uint4 vv = src[64 + u];  // V region (+512 halves)
        const __half* vh = reinterpret_cast<const __half*>(&vv);
#pragma unroll
        for (int j = 0; j < 8; j++)
            Vt[(h * 32 + d0 + j) * 72 + t] = vh[j];
    }
    for (int i = tid; i < 225 * 8; i += 512) bt[i] = bias_table[i];
    __syncthreads();

    const int warp = tid >> 5, lane = tid & 31;
    const int head = warp >> 1;
    const int q0 = (warp & 1) * 32;
    const int gr = lane >> 2;          // group row 0..7
    const int tc0 = (lane & 3) * 2;    // col pair base

    // ---- Q fragments (direct from global) ----
    int rowA[2], rowB[2];
    size_t tokA[2], tokB[2];
    uint32_t qf[2][2][4];
#pragma unroll
    for (int mi = 0; mi < 2; mi++) {
        rowA[mi] = q0 + mi * 16 + gr;
        rowB[mi] = rowA[mi] + 8;
        tokA[mi] = tokbase + (size_t)(rowA[mi] >> 3) * 256 + (rowA[mi] & 7);
        tokB[mi] = tokbase + (size_t)(rowB[mi] >> 3) * 256 + (rowB[mi] & 7);
#pragma unroll
        for (int kt = 0; kt < 2; kt++) {
            int dbase = head * 32 + kt * 16 + tc0;
            qf[mi][kt][0] = *reinterpret_cast<const uint32_t*>(qkv + tokA[mi] * 768 + dbase);
            qf[mi][kt][1] = *reinterpret_cast<const uint32_t*>(qkv + tokB[mi] * 768 + dbase);
            qf[mi][kt][2] = *reinterpret_cast<const uint32_t*>(qkv + tokA[mi] * 768 + dbase + 8);
            qf[mi][kt][3] = *reinterpret_cast<const uint32_t*>(qkv + tokB[mi] * 768 + dbase + 8);
        }
    }

    // ---- scores S = Q K^T ----
    float S[2][8][4];
#pragma unroll
    for (int mi = 0; mi < 2; mi++)
#pragma unroll
        for (int nj = 0; nj < 8; nj++)
#pragma unroll
            for (int r = 0; r < 4; r++) S[mi][nj][r] = 0.f;

#pragma unroll
    for (int nj = 0; nj < 8; nj++) {
        uint32_t bf[2][2];
#pragma unroll
        for (int kt = 0; kt < 2; kt++) {
            const __half* kp = &Ks[(head * 64 + nj * 8 + gr) * 40 + kt * 16 + tc0];
            bf[kt][0] = *reinterpret_cast<const uint32_t*>(kp);
            bf[kt][1] = *reinterpret_cast<const uint32_t*>(kp + 8);
        }
#pragma unroll
        for (int mi = 0; mi < 2; mi++)
#pragma unroll
            for (int kt = 0; kt < 2; kt++)
                mma16816(S[mi][nj], qf[mi][kt], bf[kt]);
    }

    // ---- scale + relative-position bias + softmax (unnormalized P) ----
    const float scale = 0.17677669529663687f; // 1/sqrt(32)
    float mx[2][2], sm[2][2];
#pragma unroll
    for (int mi = 0; mi < 2; mi++) {
        const int qiA = rowA[mi] >> 3, qjA = rowA[mi] & 7;
        const int qiB = rowB[mi] >> 3, qjB = rowB[mi] & 7;
        mx[mi][0] = -1e30f; mx[mi][1] = -1e30f;
#pragma unroll
        for (int nj = 0; nj < 8; nj++) {
            // ti == nj, tj == tc0 / tc0+1 (tiles are 8-aligned)
            int relA = (qiA - nj + 7) * 15 + (qjA + 7 - tc0);
            int relB = (qiB - nj + 7) * 15 + (qjB + 7 - tc0);
            S[mi][nj][0] = S[mi][nj][0] * scale + bt[relA * 8 + head];
            S[mi][nj][1] = S[mi][nj][1] * scale + bt[(relA - 1) * 8 + head];
            S[mi][nj][2] = S[mi][nj][2] * scale + bt[relB * 8 + head];
            S[mi][nj][3] = S[mi][nj][3] * scale + bt[(relB - 1) * 8 + head];
            mx[mi][0] = fmaxf(mx[mi][0], fmaxf(S[mi][nj][0], S[mi][nj][1]));
            mx[mi][1] = fmaxf(mx[mi][1], fmaxf(S[mi][nj][2], S[mi][nj][3]));
        }
        // quad reduce max (row spans lanes with same gr)
#pragma unroll
        for (int d = 1; d < 4; d <<= 1) {
            mx[mi][0] = fmaxf(mx[mi][0], __shfl_xor_sync(0xffffffffu, mx[mi][0], d));
            mx[mi][1] = fmaxf(mx[mi][1], __shfl_xor_sync(0xffffffffu, mx[mi][1], d));
        }
        sm[mi][0] = 0.f; sm[mi][1] = 0.f;
#pragma unroll
        for (int nj = 0; nj < 8; nj++) {
            S[mi][nj][0] = __expf(S[mi][nj][0] - mx[mi][0]);
            S[mi][nj][1] = __expf(S[mi][nj][1] - mx[mi][0]);
            S[mi][nj][2] = __expf(S[mi][nj][2] - mx[mi][1]);
            S[mi][nj][3] = __expf(S[mi][nj][3] - mx[mi][1]);
            sm[mi][0] += S[mi][nj][0] + S[mi][nj][1];
            sm[mi][1] += S[mi][nj][2] + S[mi][nj][3];
        }
#pragma unroll
        for (int d = 1; d < 4; d <<= 1) {
            sm[mi][0] += __shfl_xor_sync(0xffffffffu, sm[mi][0], d);
            sm[mi][1] += __shfl_xor_sync(0xffffffffu, sm[mi][1], d);
        }
    }

    // ---- O = P * V (P repacked to fp16 A-fragments via C->A layout trick) ----
    float O[2][4][4];
#pragma unroll
    for (int mi = 0; mi < 2; mi++)
#pragma unroll
        for (int dj = 0; dj < 4; dj++)
#pragma unroll
            for (int r = 0; r < 4; r++) O[mi][dj][r] = 0.f;

#pragma unroll
    for (int kt = 0; kt < 4; kt++) {
        uint32_t pa[2][4];
#pragma unroll
        for (int mi = 0; mi < 2; mi++) {
            pa[mi][0] = packh2(S[mi][2 * kt][0], S[mi][2 * kt][1]);
            pa[mi][1] = packh2(S[mi][2 * kt][2], S[mi][2 * kt][3]);
            pa[mi][2] = packh2(S[mi][2 * kt + 1][0], S[mi][2 * kt + 1][1]);
            pa[mi][3] = packh2(S[mi][2 * kt + 1][2], S[mi][2 * kt + 1][3]);
        }
#pragma unroll
        for (int dj = 0; dj < 4; dj++) {
            const __half* vp = &Vt[(head * 32 + dj * 8 + gr) * 72 + kt * 16 + tc0];
            uint32_t bf[2];
            bf[0] = *reinterpret_cast<const uint32_t*>(vp);
            bf[1] = *reinterpret_cast<const uint32_t*>(vp + 8);
#pragma unroll
            for (int mi = 0; mi < 2; mi++)
                mma16816(O[mi][dj], pa[mi], bf);
        }
    }

    // ---- epilogue: scale by 1/sum, write fp16 y ----
#pragma unroll
    for (int mi = 0; mi < 2; mi++) {
        const float rsA = 1.f / sm[mi][0];
        const float rsB = 1.f / sm[mi][1];
        __half* ypA = y + tokA[mi] * DIMC + head * 32 + tc0;
        __half* ypB = y + tokB[mi] * DIMC + head * 32 + tc0;
#pragma unroll
        for (int dj = 0; dj < 4; dj++) {
            *reinterpret_cast<uint32_t*>(ypA + dj * 8) =
                packh2(O[mi][dj][0] * rsA, O[mi][dj][1] * rsA);
            *reinterpret_cast<uint32_t*>(ypB + dj * 8) =
                packh2(O[mi][dj][2] * rsB, O[mi][dj][3] * rsB);
        }
    }
}

// ---------------------------------------------------------------------------
extern "C" void kernel_launch(void* const* d_in, const int* in_sizes, int n_in,
                              void* d_out, int out_size) {
    // metadata order: x, h, w, wqkv_w, wqkv_b, wp_w, wp_b, bias_table
    const float* x = (const float*)d_in[0];
    const float* wqkv_w = (const float*)d_in[3];
    const float* wqkv_b = (const float*)d_in[4];
    const float* wp_w = (const float*)d_in[5];
    const float* wp_b = (const float*)d_in[6];
    const float* bias_table = (const float*)d_in[7];
    float* out = (float*)d_out;

    const int M = in_sizes[0] / DIMC;  // b * 65536
    const int b = M / 65536;

    __half *qkvh, *ybuf, *xh, *wqkvh, *wph;
    cudaGetSymbolAddress((void**)&qkvh, g_qkvh);
    cudaGetSymbolAddress((void**)&ybuf, g_y);
    cudaGetSymbolAddress((void**)&xh, g_xh);
    cudaGetSymbolAddress((void**)&wqkvh, g_wqkvh);
    cudaGetSymbolAddress((void**)&wph, g_wph);

    cudaFuncSetAttribute(win_attn_mma_kernel,
                         cudaFuncAttributeMaxDynamicSharedMemorySize, ATT_SMEM);

    // 0) fp16 conversion of x and both weight matrices
    {
        int n4 = M * (DIMC / 4);
        f2h_convert_kernel<<<(n4 + 255) / 256, 256>>>(x, xh, n4);
        int w4 = 768 * (DIMC / 4);
        f2h_convert_kernel<<<(w4 + 255) / 256, 256>>>(wqkv_w, wqkvh, w4);
        int p4 = DIMC * (DIMC / 4);
        f2h_convert_kernel<<<(p4 + 255) / 256, 256>>>(wp_w, wph, p4);
    }
    // 1) QKV projection -> fp16 qkv
    {
        dim3 grid(768 / GBN, M / GBM);
        gemm_f16_kernel<__half><<<grid, 256>>>(xh, wqkvh, wqkv_b, qkvh,
                                               M, 768, DIMC);
    }
    // 2) Tensor-core window attention (one block per window)
    {
        int nblocks = b * 32 * 32;
        win_attn_mma_kernel<<<nblocks, 512, ATT_SMEM>>>(qkvh, bias_table, ybuf);
    }
    // 3) Output projection -> fp32 out
    {
        dim3 grid(DIMC / GBN, M / GBM);
        gemm_f16_kernel<float><<<grid, 256>>>(ybuf, wph, wp_b, out,
                                              M, DIMC, DIMC);
    }
}

// round 10
// speedup vs baseline: 3.3921x; 1.0252x over previous
#include <cuda_runtime.h>
#include <cuda_fp16.h>
#include <math.h>
#include <stdint.h>

// Problem constants (fixed: b=2, h=w=256, DIM=256, HEADS=8, 8x8 windows)
#define DIMC 256
#define NHEADS 8
#define HD 32
#define WSZ 64
#define MAXB 2

// Scratch (allocation-free rule: __device__ globals)
__device__ __half g_qkvh[(size_t)MAXB * 65536 * 768]; // QKV output (fp16)
__device__ __half g_y[(size_t)MAXB * 65536 * 256];    // attention output (fp16)
__device__ __half g_xh[(size_t)MAXB * 65536 * 256];   // x in fp16
__device__ __half g_wqkvh[768 * 256];                 // wqkv_w fp16
__device__ __half g_wph[256 * 256];                   // wp_w fp16

// ---------------------------------------------------------------------------
// helpers
// ---------------------------------------------------------------------------
__device__ __forceinline__ void cp16(uint32_t saddr, const void* g) {
    asm volatile("cp.async.cg.shared.global [%0], [%1], 16;" :: "r"(saddr), "l"(g));
}
__device__ __forceinline__ void mma16816(float* d, const uint32_t* a,
                                         const uint32_t* b) {
    asm volatile(
        "mma.sync.aligned.m16n8k16.row.col.f32.f16.f16.f32 "
        "{%0,%1,%2,%3}, {%4,%5,%6,%7}, {%8,%9}, {%0,%1,%2,%3};"
        : "+f"(d[0]), "+f"(d[1]), "+f"(d[2]), "+f"(d[3])
        : "r"(a[0]), "r"(a[1]), "r"(a[2]), "r"(a[3]), "r"(b[0]), "r"(b[1]));
}
__device__ __forceinline__ void ldsm4(uint32_t* r, uint32_t addr) {
    asm volatile("ldmatrix.sync.aligned.m8n8.x4.shared.b16 {%0,%1,%2,%3}, [%4];"
                 : "=r"(r[0]), "=r"(r[1]), "=r"(r[2]), "=r"(r[3]) : "r"(addr));
}
__device__ __forceinline__ void ldsm2(uint32_t* r, uint32_t addr) {
    asm volatile("ldmatrix.sync.aligned.m8n8.x2.shared.b16 {%0,%1}, [%2];"
                 : "=r"(r[0]), "=r"(r[1]) : "r"(addr));
}
__device__ __forceinline__ uint32_t packh2(float x, float y) {
    __half2 h = __floats2half2_rn(x, y);
    return *reinterpret_cast<uint32_t*>(&h);
}

// fp32 -> fp16 convert
__global__ void f2h_convert_kernel(const float* __restrict__ in,
                                   __half* __restrict__ out, int n4) {
    int i = blockIdx.x * blockDim.x + threadIdx.x;
    if (i < n4) {
        float4 v = reinterpret_cast<const float4*>(in)[i];
        uint2 p;
        p.x = packh2(v.x, v.y);
        p.y = packh2(v.z, v.w);
        reinterpret_cast<uint2*>(out)[i] = p;
    }
}

// ---------------------------------------------------------------------------
// FP16 tensor-core GEMM, fp32 accum, fused bias, templated output type:
//   C[M,N] = A[M,K](f16) * W[N,K](f16)^T + bias[N](f32)
// 128x128x32 tile, 8 warps (2x4), warp tile 64x32 via 4x4 m16n8k16.
// 3-stage cp.async ring, ldmatrix fragment loads, 1 barrier per K-iter.
// ---------------------------------------------------------------------------
#define GBM 128
#define GBN 128
#define GBK 32
#define PADH 40
#define NSTAGE 3
#define GEMM_SMEM (NSTAGE * (GBM + GBN) * PADH * 2)  // 61440 bytes

template <typename OutT>
__global__ __launch_bounds__(256, 2)
void gemm_f16_kernel(const __half* __restrict__ A, const __half* __restrict__ W,
                     const float* __restrict__ bias, OutT* __restrict__ C,
                     int M, int N, int K) {
    extern __shared__ __half smh[];
    __half* As = smh;                          // [NSTAGE][GBM][PADH]
    __half* Bs = smh + NSTAGE * GBM * PADH;    // [NSTAGE][GBN][PADH]

    const int tid = threadIdx.x;
    const int lane = tid & 31;
    const int warp = tid >> 5;
    const int wm = warp >> 2;  // 0..1
    const int wn = warp & 3;   // 0..3
    const long m0 = (long)blockIdx.y * GBM;
    const long n0 = (long)blockIdx.x * GBN;

    const uint32_t sAu = (uint32_t)__cvta_generic_to_shared(As);
    const uint32_t sBu = (uint32_t)__cvta_generic_to_shared(Bs);

    float acc[4][4][4];
#pragma unroll
    for (int mt = 0; mt < 4; mt++)
#pragma unroll
        for (int nt = 0; nt < 4; nt++)
#pragma unroll
            for (int r = 0; r < 4; r++) acc[mt][nt][r] = 0.f;

    const int NIT = K / GBK;

    auto issue = [&](int it, int stage) {
        const int k0 = it * GBK;
#pragma unroll
        for (int l = 0; l < 2; l++) {
            int idx = tid + l * 256;   // 0..511
            int r = idx >> 2;          // 0..127
            int c = idx & 3;           // 16B chunk
            cp16(sAu + ((stage * GBM + r) * PADH + c * 8) * 2,
                 A + (m0 + r) * K + k0 + c * 8);
            cp16(sBu + ((stage * GBN + r) * PADH + c * 8) * 2,
                 W + (n0 + r) * K + k0 + c * 8);
        }
        asm volatile("cp.async.commit_group;" ::: "memory");
    };

    issue(0, 0);
    issue(1, 1);

    // ldmatrix lane-derived offsets
    const int i8 = lane & 7;
    const int sub = lane >> 3;                 // 0..3
    const int arow = ((sub & 1) << 3) + i8;    // + wm*64 + mt*16
    const int acol = (sub >> 1) << 3;          // + ks
    const int brow = i8;                       // + wn*32 + nt*8  (x2: lanes 0-15)
    const int bcol = (sub & 1) << 3;           // + ks

    for (int it = 0; it < NIT; ++it) {
        if (it + 1 < NIT)
            asm volatile("cp.async.wait_group 1;" ::: "memory");
        else
            asm volatile("cp.async.wait_group 0;" ::: "memory");
        __syncthreads();

        if (it + 2 < NIT) issue(it + 2, (it + 2) % NSTAGE);

        const int st = it % NSTAGE;
        const uint32_t aBase = sAu + ((st * GBM + wm * 64 + arow) * PADH) * 2;
        const uint32_t bBase = sBu + ((st * GBN + wn * 32 + brow) * PADH) * 2;

#pragma unroll
        for (int ks = 0; ks < GBK; ks += 16) {
            uint32_t af[4][4], bf[4][2];
#pragma unroll
            for (int mt = 0; mt < 4; mt++)
                ldsm4(af[mt], aBase + (mt * 16 * PADH + ks + acol) * 2);
#pragma unroll
            for (int nt = 0; nt < 4; nt++)
                ldsm2(bf[nt], bBase + (nt * 8 * PADH + ks + bcol) * 2);
#pragma unroll
            for (int mt = 0; mt < 4; mt++)
#pragma unroll
                for (int nt = 0; nt < 4; nt++)
                    mma16816(acc[mt][nt], af[mt], bf[nt]);
        }
    }

    __syncthreads();

    // Epilogue with fused bias; OutT = float or __half
#pragma unroll
    for (int mt = 0; mt < 4; mt++) {
        long r0 = m0 + wm * 64 + mt * 16 + (lane >> 2);
#pragma unroll
        for (int nt = 0; nt < 4; nt++) {
            long c = n0 + wn * 32 + nt * 8 + 2 * (lane & 3);
            float2 b2 = *reinterpret_cast<const float2*>(&bias[c]);
            float v00 = acc[mt][nt][0] + b2.x, v01 = acc[mt][nt][1] + b2.y;
            float v10 = acc[mt][nt][2] + b2.x, v11 = acc[mt][nt][3] + b2.y;
            if (sizeof(OutT) == 4) {
                float2* p0 = reinterpret_cast<float2*>((float*)C + r0 * N + c);
                float2* p1 = reinterpret_cast<float2*>((float*)C + (r0 + 8) * N + c);
                *p0 = make_float2(v00, v01);
                *p1 = make_float2(v10, v11);
            } else {
                *reinterpret_cast<uint32_t*>((__half*)C + r0 * N + c) = packh2(v00, v01);
                *reinterpret_cast<uint32_t*>((__half*)C + (r0 + 8) * N + c) = packh2(v10, v11);
            }
        }
    }
}

// ---------------------------------------------------------------------------
// Tensor-core window attention. One block per window; 512 threads = 16 warps;
// warp = (head, query-half of 32 rows). fp16 mma for QK^T and P*V, fp32
// softmax on fragments, unnormalized P, 1/sum in epilogue. y out fp16.
// smem: Ks[8][64][40] (40960B) + Vt[8][32][72] (36864B) + bt[225*8]f32 (7200B)
// ---------------------------------------------------------------------------
#define ATT_SMEM (40960 + 36864 + 7200)

__global__ __launch_bounds__(512, 1)
void win_attn_mma_kernel(const __half* __restrict__ qkv,
                         const float* __restrict__ bias_table,
                         __half* __restrict__ y) {
    extern __shared__ char smraw[];
    __half* Ks = reinterpret_cast<__half*>(smraw);            // [8][64][40]
    __half* Vt = reinterpret_cast<__half*>(smraw + 40960);    // [8][32][72]
    float* bt = reinterpret_cast<float*>(smraw + 40960 + 36864);

    const int blk = blockIdx.x;
    const int wx = blk & 31, wy = (blk >> 5) & 31, bb = blk >> 10;
    const int tid = threadIdx.x;
    const size_t tokbase = ((size_t)bb << 16) + (size_t)wy * 8 * 256 + wx * 8;

    // ---- stage K (natural) and V (transposed) for all 8 heads ----
#pragma unroll
    for (int l = 0; l < 4; l++) {
        int idx = tid + l * 512;       // 0..2047
        int t = idx >> 5;              // token in window
        int u = idx & 31;              // uint4 within 256-half row
        int h = u >> 2;
        int d0 = (u & 3) * 8;
        size_t tok = tokbase + (size_t)(t >> 3) * 256 + (t & 7);
        const uint4* src = reinterpret_cast<const uint4*>(qkv + tok * 768);
        uint4 kk = src[32 + u];  // K region (+256 halves)
        *reinterpret_cast<uint4*>(&Ks[(h * 64 + t) * 40 + d0]) = kk;
        uint4 vv = src[64 + u];  // V region (+512 halves)
        const __half* vh = reinterpret_cast<const __half*>(&vv);
#pragma unroll
        for (int j = 0; j < 8; j++)
            Vt[(h * 32 + d0 + j) * 72 + t] = vh[j];
    }
    for (int i = tid; i < 225 * 8; i += 512) bt[i] = bias_table[i];
    __syncthreads();

    const int warp = tid >> 5, lane = tid & 31;
    const int head = warp >> 1;
    const int q0 = (warp & 1) * 32;
    const int gr = lane >> 2;          // group row 0..7
    const int tc0 = (lane & 3) * 2;    // col pair base

    // ---- Q fragments (direct from global) ----
    int rowA[2], rowB[2];
    size_t tokA[2], tokB[2];
    uint32_t qf[2][2][4];
#pragma unroll
    for (int mi = 0; mi < 2; mi++) {
        rowA[mi] = q0 + mi * 16 + gr;
        rowB[mi] = rowA[mi] + 8;
        tokA[mi] = tokbase + (size_t)(rowA[mi] >> 3) * 256 + (rowA[mi] & 7);
        tokB[mi] = tokbase + (size_t)(rowB[mi] >> 3) * 256 + (rowB[mi] & 7);
#pragma unroll
        for (int kt = 0; kt < 2; kt++) {
            int dbase = head * 32 + kt * 16 + tc0;
            qf[mi][kt][0] = *reinterpret_cast<const uint32_t*>(qkv + tokA[mi] * 768 + dbase);
            qf[mi][kt][1] = *reinterpret_cast<const uint32_t*>(qkv + tokB[mi] * 768 + dbase);
            qf[mi][kt][2] = *reinterpret_cast<const uint32_t*>(qkv + tokA[mi] * 768 + dbase + 8);
            qf[mi][kt][3] = *reinterpret_cast<const uint32_t*>(qkv + tokB[mi] * 768 + dbase + 8);
        }
    }

    // ---- scores S = Q K^T ----
    float S[2][8][4];
#pragma unroll
    for (int mi = 0; mi < 2; mi++)
#pragma unroll
        for (int nj = 0; nj < 8; nj++)
#pragma unroll
            for (int r = 0; r < 4; r++) S[mi][nj][r] = 0.f;

#pragma unroll
    for (int nj = 0; nj < 8; nj++) {
        uint32_t bf[2][2];
#pragma unroll
        for (int kt = 0; kt < 2; kt++) {
            const __half* kp = &Ks[(head * 64 + nj * 8 + gr) * 40 + kt * 16 + tc0];
            bf[kt][0] = *reinterpret_cast<const uint32_t*>(kp);
            bf[kt][1] = *reinterpret_cast<const uint32_t*>(kp + 8);
        }
#pragma unroll
        for (int mi = 0; mi < 2; mi++)
#pragma unroll
            for (int kt = 0; kt < 2; kt++)
                mma16816(S[mi][nj], qf[mi][kt], bf[kt]);
    }

    // ---- scale + relative-position bias + softmax (unnormalized P) ----
    const float scale = 0.17677669529663687f; // 1/sqrt(32)
    float mx[2][2], sm[2][2];
#pragma unroll
    for (int mi = 0; mi < 2; mi++) {
        const int qiA = rowA[mi] >> 3, qjA = rowA[mi] & 7;
        const int qiB = rowB[mi] >> 3, qjB = rowB[mi] & 7;
        mx[mi][0] = -1e30f; mx[mi][1] = -1e30f;
#pragma unroll
        for (int nj = 0; nj < 8; nj++) {
            int relA = (qiA - nj + 7) * 15 + (qjA + 7 - tc0);
            int relB = (qiB - nj + 7) * 15 + (qjB + 7 - tc0);
            S[mi][nj][0] = S[mi][nj][0] * scale + bt[relA * 8 + head];
            S[mi][nj][1] = S[mi][nj][1] * scale + bt[(relA - 1) * 8 + head];
            S[mi][nj][2] = S[mi][nj][2] * scale + bt[relB * 8 + head];
            S[mi][nj][3] = S[mi][nj][3] * scale + bt[(relB - 1) * 8 + head];
            mx[mi][0] = fmaxf(mx[mi][0], fmaxf(S[mi][nj][0], S[mi][nj][1]));
            mx[mi][1] = fmaxf(mx[mi][1], fmaxf(S[mi][nj][2], S[mi][nj][3]));
        }
#pragma unroll
        for (int d = 1; d < 4; d <<= 1) {
            mx[mi][0] = fmaxf(mx[mi][0], __shfl_xor_sync(0xffffffffu, mx[mi][0], d));
            mx[mi][1] = fmaxf(mx[mi][1], __shfl_xor_sync(0xffffffffu, mx[mi][1], d));
        }
        sm[mi][0] = 0.f; sm[mi][1] = 0.f;
#pragma unroll
        for (int nj = 0; nj < 8; nj++) {
            S[mi][nj][0] = __expf(S[mi][nj][0] - mx[mi][0]);
            S[mi][nj][1] = __expf(S[mi][nj][1] - mx[mi][0]);
            S[mi][nj][2] = __expf(S[mi][nj][2] - mx[mi][1]);
            S[mi][nj][3] = __expf(S[mi][nj][3] - mx[mi][1]);
            sm[mi][0] += S[mi][nj][0] + S[mi][nj][1];
            sm[mi][1] += S[mi][nj][2] + S[mi][nj][3];
        }
#pragma unroll
        for (int d = 1; d < 4; d <<= 1) {
            sm[mi][0] += __shfl_xor_sync(0xffffffffu, sm[mi][0], d);
            sm[mi][1] += __shfl_xor_sync(0xffffffffu, sm[mi][1], d);
        }
    }

    // ---- O = P * V (P repacked to fp16 A-fragments) ----
    float O[2][4][4];
#pragma unroll
    for (int mi = 0; mi < 2; mi++)
#pragma unroll
        for (int dj = 0; dj < 4; dj++)
#pragma unroll
            for (int r = 0; r < 4; r++) O[mi][dj][r] = 0.f;

#pragma unroll
    for (int kt = 0; kt < 4; kt++) {
        uint32_t pa[2][4];
#pragma unroll
        for (int mi = 0; mi < 2; mi++) {
            pa[mi][0] = packh2(S[mi][2 * kt][0], S[mi][2 * kt][1]);
            pa[mi][1] = packh2(S[mi][2 * kt][2], S[mi][2 * kt][3]);
            pa[mi][2] = packh2(S[mi][2 * kt + 1][0], S[mi][2 * kt + 1][1]);
            pa[mi][3] = packh2(S[mi][2 * kt + 1][2], S[mi][2 * kt + 1][3]);
        }
#pragma unroll
        for (int dj = 0; dj < 4; dj++) {
            const __half* vp = &Vt[(head * 32 + dj * 8 + gr) * 72 + kt * 16 + tc0];
            uint32_t bf[2];
            bf[0] = *reinterpret_cast<const uint32_t*>(vp);
            bf[1] = *reinterpret_cast<const uint32_t*>(vp + 8);
#pragma unroll
            for (int mi = 0; mi < 2; mi++)
                mma16816(O[mi][dj], pa[mi], bf);
        }
    }

    // ---- epilogue: scale by 1/sum, write fp16 y ----
#pragma unroll
    for (int mi = 0; mi < 2; mi++) {
        const float rsA = 1.f / sm[mi][0];
        const float rsB = 1.f / sm[mi][1];
        __half* ypA = y + tokA[mi] * DIMC + head * 32 + tc0;
        __half* ypB = y + tokB[mi] * DIMC + head * 32 + tc0;
#pragma unroll
        for (int dj = 0; dj < 4; dj++) {
            *reinterpret_cast<uint32_t*>(ypA + dj * 8) =
                packh2(O[mi][dj][0] * rsA, O[mi][dj][1] * rsA);
            *reinterpret_cast<uint32_t*>(ypB + dj * 8) =
                packh2(O[mi][dj][2] * rsB, O[mi][dj][3] * rsB);
        }
    }
}

// ---------------------------------------------------------------------------
extern "C" void kernel_launch(void* const* d_in, const int* in_sizes, int n_in,
                              void* d_out, int out_size) {
    // metadata order: x, h, w, wqkv_w, wqkv_b, wp_w, wp_b, bias_table
    const float* x = (const float*)d_in[0];
    const float* wqkv_w = (const float*)d_in[3];
    const float* wqkv_b = (const float*)d_in[4];
    const float* wp_w = (const float*)d_in[5];
    const float* wp_b = (const float*)d_in[6];
    const float* bias_table = (const float*)d_in[7];
    float* out = (float*)d_out;

    const int M = in_sizes[0] / DIMC;  // b * 65536
    const int b = M / 65536;

    __half *qkvh, *ybuf, *xh, *wqkvh, *wph;
    cudaGetSymbolAddress((void**)&qkvh, g_qkvh);
    cudaGetSymbolAddress((void**)&ybuf, g_y);
    cudaGetSymbolAddress((void**)&xh, g_xh);
    cudaGetSymbolAddress((void**)&wqkvh, g_wqkvh);
    cudaGetSymbolAddress((void**)&wph, g_wph);

    cudaFuncSetAttribute(win_attn_mma_kernel,
                         cudaFuncAttributeMaxDynamicSharedMemorySize, ATT_SMEM);
    cudaFuncSetAttribute(gemm_f16_kernel<__half>,
                         cudaFuncAttributeMaxDynamicSharedMemorySize, GEMM_SMEM);
    cudaFuncSetAttribute(gemm_f16_kernel<float>,
                         cudaFuncAttributeMaxDynamicSharedMemorySize, GEMM_SMEM);

    // 0) fp16 conversion of x and both weight matrices
    {
        int n4 = M * (DIMC / 4);
        f2h_convert_kernel<<<(n4 + 255) / 256, 256>>>(x, xh, n4);
        int w4 = 768 * (DIMC / 4);
        f2h_convert_kernel<<<(w4 + 255) / 256, 256>>>(wqkv_w, wqkvh, w4);
        int p4 = DIMC * (DIMC / 4);
        f2h_convert_kernel<<<(p4 + 255) / 256, 256>>>(wp_w, wph, p4);
    }
    // 1) QKV projection -> fp16 qkv
    {
        dim3 grid(768 / GBN, M / GBM);
        gemm_f16_kernel<__half><<<grid, 256, GEMM_SMEM>>>(xh, wqkvh, wqkv_b,
                                                          qkvh, M, 768, DIMC);
    }
    // 2) Tensor-core window attention (one block per window)
    {
        int nblocks = b * 32 * 32;
        win_attn_mma_kernel<<<nblocks, 512, ATT_SMEM>>>(qkvh, bias_table, ybuf);
    }
    // 3) Output projection -> fp32 out
    {
        dim3 grid(DIMC / GBN, M / GBM);
        gemm_f16_kernel<float><<<grid, 256, GEMM_SMEM>>>(ybuf, wph, wp_b, out,
                                                         M, DIMC, DIMC);
    }
}